// round 5
// baseline (speedup 1.0000x reference)
#include <cuda_runtime.h>

#define U 128
#define ROW_IN  (4 * U)   // 512 floats per x1 row
#define ROW_OUT (11 * U)  // 1408 floats per output row

__global__ __launch_bounds__(128, 8)
void ChannelWiseTensorProduct_85779086836293_kernel(
    const float* __restrict__ x1,
    const float* __restrict__ x2,
    const float* __restrict__ w,
    float* __restrict__ out)
{
    __shared__ float sin_row[ROW_IN];
    __shared__ float sout_row[ROW_OUT];
    __shared__ float sy[4];

    const int b = blockIdx.x;
    const int t = threadIdx.x;

    // --- Load x1 row (512 floats) fully coalesced as float4 ---
    const float4* x1v = reinterpret_cast<const float4*>(x1 + (size_t)b * ROW_IN);
    reinterpret_cast<float4*>(sin_row)[t] = x1v[t];

    // --- Load x2 row (4 floats) ---
    if (t < 4) sy[t] = x2[(size_t)b * 4 + t];

    __syncthreads();

    const float y0  = sy[0];
    const float y10 = sy[1];
    const float y11 = sy[2];
    const float y12 = sy[3];

    // Per-channel inputs: s0[u], s1[u][0..2]
    const float s0 = sin_row[t];
    const float a0 = sin_row[U + 3 * t + 0];
    const float a1 = sin_row[U + 3 * t + 1];
    const float a2 = sin_row[U + 3 * t + 2];

    // Weights (broadcast across blocks; L1/L2 resident)
    const float w0 = w[t];
    const float w1 = w[U + t];
    const float w2 = w[2 * U + t];
    const float w3 = w[3 * U + t];
    const float w4 = w[4 * U + t];

    const float INV_SQRT3 = 0.57735026918962576451f;
    const float INV_SQRT2 = 0.70710678118654752440f;

    // o0[u] = w0 * s0 * y0
    sout_row[t] = w0 * s0 * y0;

    // o1[u,j] = w1 * s0 * y1[j]
    const float ws0 = w1 * s0;
    sout_row[U + 3 * t + 0] = ws0 * y10;
    sout_row[U + 3 * t + 1] = ws0 * y11;
    sout_row[U + 3 * t + 2] = ws0 * y12;

    // o2[u,i] = w2 * s1[u,i] * y0
    const float wy = w2 * y0;
    sout_row[4 * U + 3 * t + 0] = wy * a0;
    sout_row[4 * U + 3 * t + 1] = wy * a1;
    sout_row[4 * U + 3 * t + 2] = wy * a2;

    // o3[u] = w3 * dot(s1[u], y1) / sqrt(3)
    sout_row[7 * U + t] = w3 * (a0 * y10 + a1 * y11 + a2 * y12) * INV_SQRT3;

    // o4[u,k] = w4 * cross(s1[u], y1)[k] / sqrt(2)
    const float c0 = a1 * y12 - a2 * y11;
    const float c1 = a2 * y10 - a0 * y12;
    const float c2 = a0 * y11 - a1 * y10;
    const float w4s = w4 * INV_SQRT2;
    sout_row[8 * U + 3 * t + 0] = w4s * c0;
    sout_row[8 * U + 3 * t + 1] = w4s * c1;
    sout_row[8 * U + 3 * t + 2] = w4s * c2;

    __syncthreads();

    // --- Flush output row (1408 floats = 352 float4) fully coalesced ---
    float4* ov = reinterpret_cast<float4*>(out + (size_t)b * ROW_OUT);
    const float4* sv = reinterpret_cast<const float4*>(sout_row);
    #pragma unroll
    for (int i = t; i < ROW_OUT / 4; i += 128) {
        ov[i] = sv[i];
    }
}

extern "C" void kernel_launch(void* const* d_in, const int* in_sizes, int n_in,
                              void* d_out, int out_size) {
    const float* x1 = (const float*)d_in[0];
    const float* x2 = (const float*)d_in[1];
    const float* w  = (const float*)d_in[2];
    float* out = (float*)d_out;

    const int B = in_sizes[0] / ROW_IN;  // 65536
    ChannelWiseTensorProduct_85779086836293_kernel<<<B, 128>>>(x1, x2, w, out);
}

// round 6
// speedup vs baseline: 1.0037x; 1.0037x over previous
#include <cuda_runtime.h>

#define U 128
#define ROW_IN  (4 * U)   // 512 floats per x1 row
#define ROW_OUT (11 * U)  // 1408 floats per output row

__global__ __launch_bounds__(128, 8)
void ChannelWiseTensorProduct_85779086836293_kernel(
    const float* __restrict__ x1,
    const float* __restrict__ x2,
    const float* __restrict__ w,
    float* __restrict__ out)
{
    __shared__ float sin_row[ROW_IN];
    __shared__ float sout_vec[3 * 3 * U];   // staged o1 | o2 | o4 (384 floats each)
    __shared__ float sy[4];

    const int b = blockIdx.x;
    const int t = threadIdx.x;

    // --- Load x1 row (512 floats), streaming (no reuse) ---
    const float4* x1v = reinterpret_cast<const float4*>(x1 + (size_t)b * ROW_IN);
    reinterpret_cast<float4*>(sin_row)[t] = __ldcs(&x1v[t]);

    // --- Load x2 row (4 floats), streaming ---
    if (t < 4) sy[t] = __ldcs(&x2[(size_t)b * 4 + t]);

    __syncthreads();

    const float y0  = sy[0];
    const float y10 = sy[1];
    const float y11 = sy[2];
    const float y12 = sy[3];

    // Per-channel inputs: s0[u], s1[u][0..2]
    const float s0 = sin_row[t];
    const float a0 = sin_row[U + 3 * t + 0];
    const float a1 = sin_row[U + 3 * t + 1];
    const float a2 = sin_row[U + 3 * t + 2];

    // Weights (broadcast across blocks; keep cached)
    const float w0 = w[t];
    const float w1 = w[U + t];
    const float w2 = w[2 * U + t];
    const float w3 = w[3 * U + t];
    const float w4 = w[4 * U + t];

    const float INV_SQRT3 = 0.57735026918962576451f;
    const float INV_SQRT2 = 0.70710678118654752440f;

    float* orow = out + (size_t)b * ROW_OUT;

    // o0[u] = w0 * s0 * y0  — direct coalesced scalar store (full lines/warp)
    __stcs(&orow[t], w0 * s0 * y0);

    // o3[u] = w3 * dot(s1[u], y1) / sqrt(3) — direct coalesced scalar store
    __stcs(&orow[7 * U + t], w3 * (a0 * y10 + a1 * y11 + a2 * y12) * INV_SQRT3);

    // o1[u,j] = w1 * s0 * y1[j]  -> staged at sout_vec[0..384)
    const float ws0 = w1 * s0;
    sout_vec[3 * t + 0] = ws0 * y10;
    sout_vec[3 * t + 1] = ws0 * y11;
    sout_vec[3 * t + 2] = ws0 * y12;

    // o2[u,i] = w2 * y0 * s1[u,i] -> staged at sout_vec[384..768)
    const float wy = w2 * y0;
    sout_vec[3 * U + 3 * t + 0] = wy * a0;
    sout_vec[3 * U + 3 * t + 1] = wy * a1;
    sout_vec[3 * U + 3 * t + 2] = wy * a2;

    // o4[u,k] = w4 * cross(s1[u], y1)[k] / sqrt(2) -> staged at sout_vec[768..1152)
    const float c0 = a1 * y12 - a2 * y11;
    const float c1 = a2 * y10 - a0 * y12;
    const float c2 = a0 * y11 - a1 * y10;
    const float w4s = w4 * INV_SQRT2;
    sout_vec[6 * U + 3 * t + 0] = w4s * c0;
    sout_vec[6 * U + 3 * t + 1] = w4s * c1;
    sout_vec[6 * U + 3 * t + 2] = w4s * c2;

    __syncthreads();

    // --- Flush the three staged 3-vector segments (288 float4s), streaming stores.
    // Staged float4 index i in [0,288): segment = i/96, offset-in-segment = i%96.
    // Global float4 bases: o1 -> 32 (float 128), o2 -> 128 (float 512), o4 -> 256 (float 1024).
    float4* ov = reinterpret_cast<float4*>(orow);
    const float4* sv = reinterpret_cast<const float4*>(sout_vec);

    {
        // i = t  (segment 0 for t<96, segment 1 for t>=96)
        const int i = t;
        const int seg = i / 96;
        const int off = i - seg * 96;
        const int gbase = (seg == 0) ? 32 : 128;
        __stcs(&ov[gbase + off], sv[i]);
    }
    {
        // i = t + 128 (segment 1 for t<64, segment 2 for t>=64)
        const int i = t + 128;
        const int seg = i / 96;
        const int off = i - seg * 96;
        const int gbase = (seg == 1) ? 128 : 256;
        __stcs(&ov[gbase + off], sv[i]);
    }
    if (t < 32) {
        // i = t + 256 (segment 2)
        const int i = t + 256;
        const int off = i - 192;
        __stcs(&ov[256 + off], sv[i]);
    }
}

extern "C" void kernel_launch(void* const* d_in, const int* in_sizes, int n_in,
                              void* d_out, int out_size) {
    const float* x1 = (const float*)d_in[0];
    const float* x2 = (const float*)d_in[1];
    const float* w  = (const float*)d_in[2];
    float* out = (float*)d_out;

    const int B = in_sizes[0] / ROW_IN;  // 65536
    ChannelWiseTensorProduct_85779086836293_kernel<<<B, 128>>>(x1, x2, w, out);
}